// round 6
// baseline (speedup 1.0000x reference)
#include <cuda_runtime.h>
#include <math.h>

#define NHN 50000          // head nodes
#define NTN 50000          // tail nodes
#define NE  1600000        // edges
#define INF 256            // in features
#define OUTF 32
#define NHEAD 4
#define EDGEF 64
#define NET 5
#define FOUT 128           // NHEAD*OUTF
#define NSLOPE 0.2f

// ---------------- static scratch ----------------
__device__ __align__(16) float    g_htail[(size_t)NTN * FOUT];   // 25.6MB
__device__ __align__(16) float    g_hl[NHN * NHEAD];
__device__ __align__(16) float    g_hr[NTN * NHEAD];
__device__ __align__(16) float    g_he[NET * NHEAD];
__device__ __align__(16) float    g_Wl[NHEAD * INF];
__device__ __align__(16) float    g_Wr[NHEAD * INF];
__device__ __align__(16) unsigned g_menc[NHN * NHEAD];
__device__ __align__(16) float    g_m[NHN * NHEAD];
__device__ __align__(16) float    g_den[NHN * NHEAD];
__device__ __align__(16) float    g_ex[(size_t)NE * NHEAD];      // att, then exp
__device__ int g_idx64;   // 1 if index arrays are int64, 0 if int32

// ---- robust index fetch: works for int32 or int64 input, clamped in-range ----
__device__ __forceinline__ int fetch_idx(const void* buf, int i, int n, int is64) {
    long long v = is64 ? ((const long long*)buf)[i] : (long long)((const int*)buf)[i];
    int r = (int)v;
    if (r < 0) r = 0;
    if (r >= n) r = n - 1;
    return r;
}

// order-preserving float<->uint encoding for atomicMax
__device__ __forceinline__ unsigned fenc(float f) {
    unsigned u = __float_as_uint(f);
    return (u & 0x80000000u) ? ~u : (u | 0x80000000u);
}
__device__ __forceinline__ float fdec(unsigned u) {
    return (u & 0x80000000u) ? __uint_as_float(u & 0x7FFFFFFFu)
                             : __uint_as_float(~u);
}

// ---------------- dtype detection for index arrays ----------------
// For little-endian int64 values in [0, 50000), every odd 32-bit word is 0.
// For int32 random values, 64 consecutive zeros is impossible in practice.
__global__ void detect_kernel(const unsigned* __restrict__ el_raw) {
    if (threadIdx.x == 0) {
        int all0 = 1;
        #pragma unroll 8
        for (int i = 0; i < 64; i++)
            if (el_raw[2 * i + 1] != 0u) all0 = 0;
        g_idx64 = all0;
    }
}

// ---------------- tiny prep: folded projection vectors ----------------
__global__ void prep_kernel(const float* __restrict__ W, const float* __restrict__ We,
                            const float* __restrict__ emb,
                            const float* __restrict__ a_l, const float* __restrict__ a_r,
                            const float* __restrict__ a_e) {
    int tid = threadIdx.x;
    // Wl[h][k] = sum_d W[k, h*32+d] * a_l[h,d]   (and Wr with a_r)
    for (int idx = tid; idx < NHEAD * INF; idx += blockDim.x) {
        int h = idx >> 8;       // / 256
        int k = idx & 255;
        float sl = 0.f, sr = 0.f;
        #pragma unroll
        for (int d = 0; d < OUTF; d++) {
            float w = W[k * FOUT + h * OUTF + d];
            sl += w * a_l[h * OUTF + d];
            sr += w * a_r[h * OUTF + d];
        }
        g_Wl[idx] = sl;
        g_Wr[idx] = sr;
    }
    // he[t][h] = sum_f a_e[h,f] * (emb[t,:] @ We[:, h*64+f])
    for (int idx = tid; idx < NET * NHEAD; idx += blockDim.x) {
        int t = idx / NHEAD, h = idx % NHEAD;
        float s = 0.f;
        for (int f = 0; f < EDGEF; f++) {
            float ef = 0.f;
            #pragma unroll 8
            for (int k = 0; k < EDGEF; k++)
                ef += emb[t * EDGEF + k] * We[k * (NHEAD * EDGEF) + h * EDGEF + f];
            s += a_e[h * EDGEF + f] * ef;
        }
        g_he[t * NHEAD + h] = s;
    }
}

// ---------------- init: zero accumulators ----------------
__global__ void init_kernel(float* __restrict__ out) {
    int i = blockIdx.x * blockDim.x + threadIdx.x;
    int stride = gridDim.x * blockDim.x;
    float4 z = make_float4(0.f, 0.f, 0.f, 0.f);
    for (int j = i; j < NHN * FOUT / 4; j += stride)
        reinterpret_cast<float4*>(out)[j] = z;
    for (int j = i; j < NHN * NHEAD; j += stride) {
        g_menc[j] = 0u;
        g_den[j]  = 0.f;
    }
}

// ---------------- per-node logits: hl = head@Wl, hr = tail@Wr ----------------
__global__ void logits_kernel(const float* __restrict__ headf,
                              const float* __restrict__ tailf) {
    int gw   = (blockIdx.x * blockDim.x + threadIdx.x) >> 5;
    int lane = threadIdx.x & 31;
    if (gw >= NHN + NTN) return;
    const float* src; const float* Wp; float* dst; int row;
    if (gw < NHN) { row = gw;        src = headf; Wp = g_Wl; dst = g_hl; }
    else          { row = gw - NHN;  src = tailf; Wp = g_Wr; dst = g_hr; }

    const float4* x = reinterpret_cast<const float4*>(src + (size_t)row * INF);
    float4 x0 = x[lane];
    float4 x1 = x[lane + 32];
    float p[NHEAD];
    #pragma unroll
    for (int h = 0; h < NHEAD; h++) {
        const float4* w = reinterpret_cast<const float4*>(Wp + h * INF);
        float4 w0 = w[lane], w1 = w[lane + 32];
        p[h] = x0.x*w0.x + x0.y*w0.y + x0.z*w0.z + x0.w*w0.w
             + x1.x*w1.x + x1.y*w1.y + x1.z*w1.z + x1.w*w1.w;
    }
    #pragma unroll
    for (int off = 16; off; off >>= 1) {
        #pragma unroll
        for (int h = 0; h < NHEAD; h++)
            p[h] += __shfl_xor_sync(0xffffffffu, p[h], off);
    }
    if (lane == 0)
        *reinterpret_cast<float4*>(&dst[row * NHEAD]) = make_float4(p[0], p[1], p[2], p[3]);
}

// ---------------- tail GEMM: h_tail = tail_feature @ W  (50000x256x128) ----------------
__global__ void __launch_bounds__(256, 2)
gemm_tail_kernel(const float* __restrict__ X, const float* __restrict__ W) {
    __shared__ float As[8][128];
    __shared__ float Bs[8][128];
    int tid = threadIdx.x;
    int tx = tid & 15, ty = tid >> 4;
    int rbase = blockIdx.x * 128;

    float acc[8][8];
    #pragma unroll
    for (int i = 0; i < 8; i++)
        #pragma unroll
        for (int j = 0; j < 8; j++) acc[i][j] = 0.f;

    for (int k0 = 0; k0 < INF; k0 += 8) {
        {
            int arow = rbase + (tid >> 1);
            int ar = arow < NTN ? arow : NTN - 1;
            const float4 av = *reinterpret_cast<const float4*>(
                X + (size_t)ar * INF + k0 + (tid & 1) * 4);
            int kp = (tid & 1) * 4;
            int rr = tid >> 1;
            As[kp + 0][rr] = av.x;
            As[kp + 1][rr] = av.y;
            As[kp + 2][rr] = av.z;
            As[kp + 3][rr] = av.w;
        }
        {
            const float4 bv = *reinterpret_cast<const float4*>(
                W + (size_t)(k0 + (tid >> 5)) * FOUT + (tid & 31) * 4);
            *reinterpret_cast<float4*>(&Bs[tid >> 5][(tid & 31) * 4]) = bv;
        }
        __syncthreads();
        #pragma unroll
        for (int kk = 0; kk < 8; kk++) {
            float a[8], b[8];
            float4 t0 = *reinterpret_cast<const float4*>(&As[kk][ty * 4]);
            float4 t1 = *reinterpret_cast<const float4*>(&As[kk][64 + ty * 4]);
            a[0]=t0.x; a[1]=t0.y; a[2]=t0.z; a[3]=t0.w;
            a[4]=t1.x; a[5]=t1.y; a[6]=t1.z; a[7]=t1.w;
            float4 u0 = *reinterpret_cast<const float4*>(&Bs[kk][tx * 4]);
            float4 u1 = *reinterpret_cast<const float4*>(&Bs[kk][64 + tx * 4]);
            b[0]=u0.x; b[1]=u0.y; b[2]=u0.z; b[3]=u0.w;
            b[4]=u1.x; b[5]=u1.y; b[6]=u1.z; b[7]=u1.w;
            #pragma unroll
            for (int i = 0; i < 8; i++)
                #pragma unroll
                for (int j = 0; j < 8; j++)
                    acc[i][j] += a[i] * b[j];
        }
        __syncthreads();
    }
    #pragma unroll
    for (int i = 0; i < 8; i++) {
        int r = rbase + (i < 4 ? ty * 4 + i : 64 + ty * 4 + (i - 4));
        if (r < NTN) {
            *reinterpret_cast<float4*>(&g_htail[(size_t)r * FOUT + tx * 4]) =
                make_float4(acc[i][0], acc[i][1], acc[i][2], acc[i][3]);
            *reinterpret_cast<float4*>(&g_htail[(size_t)r * FOUT + 64 + tx * 4]) =
                make_float4(acc[i][4], acc[i][5], acc[i][6], acc[i][7]);
        }
    }
}

// ---------------- edge pass 1: att + segment max ----------------
__global__ void edge1_kernel(const void* __restrict__ el,
                             const void* __restrict__ te) {
    int e = blockIdx.x * blockDim.x + threadIdx.x;
    if (e >= NE) return;
    int is64 = g_idx64;
    int hi = fetch_idx(el, e, NHN, is64);
    int ti = fetch_idx(el, NE + e, NTN, is64);
    int tt = fetch_idx(te, e, NET, is64);
    float4 l = *reinterpret_cast<const float4*>(&g_hl[hi * NHEAD]);
    float4 r = *reinterpret_cast<const float4*>(&g_hr[ti * NHEAD]);
    float4 h = *reinterpret_cast<const float4*>(&g_he[tt * NHEAD]);
    float4 a;
    a.x = l.x + r.x + h.x; a.x = a.x >= 0.f ? a.x : NSLOPE * a.x;
    a.y = l.y + r.y + h.y; a.y = a.y >= 0.f ? a.y : NSLOPE * a.y;
    a.z = l.z + r.z + h.z; a.z = a.z >= 0.f ? a.z : NSLOPE * a.z;
    a.w = l.w + r.w + h.w; a.w = a.w >= 0.f ? a.w : NSLOPE * a.w;
    *reinterpret_cast<float4*>(&g_ex[(size_t)e * NHEAD]) = a;
    atomicMax(&g_menc[hi * NHEAD + 0], fenc(a.x));
    atomicMax(&g_menc[hi * NHEAD + 1], fenc(a.y));
    atomicMax(&g_menc[hi * NHEAD + 2], fenc(a.z));
    atomicMax(&g_menc[hi * NHEAD + 3], fenc(a.w));
}

// ---------------- decode max (0 for empty rows, matches isfinite fixup) ----------------
__global__ void decode_kernel() {
    int i = blockIdx.x * blockDim.x + threadIdx.x;
    if (i >= NHN * NHEAD) return;
    unsigned u = g_menc[i];
    g_m[i] = u ? fdec(u) : 0.f;
}

// ---------------- edge pass 2: exp + segment sum ----------------
__global__ void edge2_kernel(const void* __restrict__ el) {
    int e = blockIdx.x * blockDim.x + threadIdx.x;
    if (e >= NE) return;
    int hi = fetch_idx(el, e, NHN, g_idx64);
    float4 a = *reinterpret_cast<const float4*>(&g_ex[(size_t)e * NHEAD]);
    float4 m = *reinterpret_cast<const float4*>(&g_m[hi * NHEAD]);
    float4 ex;
    ex.x = expf(a.x - m.x);
    ex.y = expf(a.y - m.y);
    ex.z = expf(a.z - m.z);
    ex.w = expf(a.w - m.w);
    *reinterpret_cast<float4*>(&g_ex[(size_t)e * NHEAD]) = ex;
    atomicAdd(&g_den[hi * NHEAD + 0], ex.x);
    atomicAdd(&g_den[hi * NHEAD + 1], ex.y);
    atomicAdd(&g_den[hi * NHEAD + 2], ex.z);
    atomicAdd(&g_den[hi * NHEAD + 3], ex.w);
}

// ---------------- invert denominators ----------------
__global__ void recip_kernel() {
    int i = blockIdx.x * blockDim.x + threadIdx.x;
    if (i >= NHN * NHEAD) return;
    float d = g_den[i];
    g_den[i] = 1.0f / d;   // inf for empty rows: never read
}

// ---------------- edge pass 3: alpha + aggregation (warp per edge) ----------------
__global__ void edge3_kernel(const void* __restrict__ el,
                             float* __restrict__ outacc,
                             float* __restrict__ alpha_out,
                             int write_alpha) {
    int warp = (blockIdx.x * blockDim.x + threadIdx.x) >> 5;
    int lane = threadIdx.x & 31;
    if (warp >= NE) return;
    int is64 = g_idx64;
    int hi = fetch_idx(el, warp, NHN, is64);
    int ti = fetch_idx(el, NE + warp, NTN, is64);
    float4 ex = *reinterpret_cast<const float4*>(&g_ex[(size_t)warp * NHEAD]);
    float4 rd = *reinterpret_cast<const float4*>(&g_den[hi * NHEAD]);
    float4 al = make_float4(ex.x * rd.x, ex.y * rd.y, ex.z * rd.z, ex.w * rd.w);
    if (write_alpha && lane == 0)
        *reinterpret_cast<float4*>(&alpha_out[(size_t)warp * NHEAD]) = al;
    int h = lane >> 3;   // head index for this lane's float4
    float a = (h == 0) ? al.x : (h == 1) ? al.y : (h == 2) ? al.z : al.w;
    float4 v = *reinterpret_cast<const float4*>(&g_htail[(size_t)ti * FOUT + lane * 4]);
    float* dst = outacc + (size_t)hi * FOUT + lane * 4;
    asm volatile("red.global.add.v4.f32 [%0], {%1,%2,%3,%4};"
                 :: "l"(dst), "f"(v.x * a), "f"(v.y * a), "f"(v.z * a), "f"(v.w * a)
                 : "memory");
}

// ---------------- final ELU (in place) ----------------
__global__ void elu_kernel(float* __restrict__ out) {
    int i = blockIdx.x * blockDim.x + threadIdx.x;
    if (i >= NHN * FOUT / 4) return;
    float4 v = reinterpret_cast<const float4*>(out)[i];
    v.x = v.x > 0.f ? v.x : expm1f(v.x);
    v.y = v.y > 0.f ? v.y : expm1f(v.y);
    v.z = v.z > 0.f ? v.z : expm1f(v.z);
    v.w = v.w > 0.f ? v.w : expm1f(v.w);
    reinterpret_cast<float4*>(out)[i] = v;
}

extern "C" void kernel_launch(void* const* d_in, const int* in_sizes, int n_in,
                              void* d_out, int out_size) {
    const float* headf = (const float*)d_in[0];
    const float* tailf = (const float*)d_in[1];
    const float* W     = (const float*)d_in[2];
    const float* We    = (const float*)d_in[3];
    const float* emb   = (const float*)d_in[4];
    const float* a_l   = (const float*)d_in[5];
    const float* a_r   = (const float*)d_in[6];
    const float* a_e   = (const float*)d_in[7];
    const void*  el    = d_in[8];
    const void*  te    = d_in[9];

    float* out   = (float*)d_out;
    float* alpha = out + (size_t)NHN * FOUT;
    int write_alpha = (out_size >= NHN * FOUT + NE * NHEAD) ? 1 : 0;

    detect_kernel<<<1, 32>>>((const unsigned*)el);
    prep_kernel<<<1, 256>>>(W, We, emb, a_l, a_r, a_e);
    init_kernel<<<1024, 256>>>(out);
    logits_kernel<<<((NHN + NTN) + 7) / 8, 256>>>(headf, tailf);
    gemm_tail_kernel<<<(NTN + 127) / 128, 256>>>(tailf, W);
    edge1_kernel<<<(NE + 255) / 256, 256>>>(el, te);
    decode_kernel<<<(NHN * NHEAD + 255) / 256, 256>>>();
    edge2_kernel<<<(NE + 255) / 256, 256>>>(el);
    recip_kernel<<<(NHN * NHEAD + 255) / 256, 256>>>();
    edge3_kernel<<<NE / 8, 256>>>(el, out, alpha, write_alpha);
    elu_kernel<<<(NHN * FOUT / 4 + 255) / 256, 256>>>(out);
}

// round 10
// speedup vs baseline: 1.1866x; 1.1866x over previous
#include <cuda_runtime.h>
#include <math.h>

#define NHN 50000          // head nodes
#define NTN 50000          // tail nodes
#define NE  1600000        // edges
#define INF 256            // in features
#define OUTF 32
#define NHEAD 4
#define EDGEF 64
#define NET 5
#define FOUT 128           // NHEAD*OUTF
#define NSLOPE 0.2f

// ---------------- sorted edge record (one 32B sector) ----------------
struct __align__(32) SEdge {
    float ex[4];   // exp(att) per head
    int   ti;      // tail index
    int   e;       // original edge id (for alpha output)
    int   pad[2];
};

// ---------------- static scratch ----------------
__device__ __align__(16) float g_htail[(size_t)NTN * FOUT];   // 25.6MB
__device__ __align__(16) float g_hl[NHN * NHEAD];
__device__ __align__(16) float g_hr[NTN * NHEAD];
__device__ __align__(16) float g_he[NET * NHEAD];
__device__ __align__(16) float g_Wl[NHEAD * INF];
__device__ __align__(16) float g_Wr[NHEAD * INF];
__device__ __align__(16) float g_den[NHN * NHEAD];
__device__ int   g_cnt[NHN];
__device__ int   g_ptr[NHN + 1];
__device__ int   g_cur[NHN];
__device__ SEdge g_srt[NE];                                   // 51.2MB
__device__ int   g_idx64;   // 1 if index arrays are int64, 0 if int32

// ---- robust index fetch: works for int32 or int64 input, clamped in-range ----
__device__ __forceinline__ int fetch_idx(const void* buf, int i, int n, int is64) {
    long long v = is64 ? ((const long long*)buf)[i] : (long long)((const int*)buf)[i];
    int r = (int)v;
    if (r < 0) r = 0;
    if (r >= n) r = n - 1;
    return r;
}

// ---------------- dtype detection for index arrays ----------------
// For little-endian int64 values in [0, 50000), every odd 32-bit word is 0.
__global__ void detect_kernel(const unsigned* __restrict__ el_raw) {
    if (threadIdx.x == 0) {
        int all0 = 1;
        #pragma unroll 8
        for (int i = 0; i < 64; i++)
            if (el_raw[2 * i + 1] != 0u) all0 = 0;
        g_idx64 = all0;
    }
}

// ---------------- tiny prep: folded projection vectors ----------------
__global__ void prep_kernel(const float* __restrict__ W, const float* __restrict__ We,
                            const float* __restrict__ emb,
                            const float* __restrict__ a_l, const float* __restrict__ a_r,
                            const float* __restrict__ a_e) {
    int tid = threadIdx.x;
    // Wl[h][k] = sum_d W[k, h*32+d] * a_l[h,d]   (and Wr with a_r)
    for (int idx = tid; idx < NHEAD * INF; idx += blockDim.x) {
        int h = idx >> 8;
        int k = idx & 255;
        float sl = 0.f, sr = 0.f;
        #pragma unroll
        for (int d = 0; d < OUTF; d++) {
            float w = W[k * FOUT + h * OUTF + d];
            sl += w * a_l[h * OUTF + d];
            sr += w * a_r[h * OUTF + d];
        }
        g_Wl[idx] = sl;
        g_Wr[idx] = sr;
    }
    // he[t][h] = sum_f a_e[h,f] * (emb[t,:] @ We[:, h*64+f])
    for (int idx = tid; idx < NET * NHEAD; idx += blockDim.x) {
        int t = idx / NHEAD, h = idx % NHEAD;
        float s = 0.f;
        for (int f = 0; f < EDGEF; f++) {
            float ef = 0.f;
            #pragma unroll 8
            for (int k = 0; k < EDGEF; k++)
                ef += emb[t * EDGEF + k] * We[k * (NHEAD * EDGEF) + h * EDGEF + f];
            s += a_e[h * EDGEF + f] * ef;
        }
        g_he[t * NHEAD + h] = s;
    }
}

// ---------------- init: zero den + counts ----------------
__global__ void init_kernel() {
    int i = blockIdx.x * blockDim.x + threadIdx.x;
    int stride = gridDim.x * blockDim.x;
    for (int j = i; j < NHN * NHEAD; j += stride) g_den[j] = 0.f;
    for (int j = i; j < NHN; j += stride) g_cnt[j] = 0;
}

// ---------------- per-node logits: 4 rows per warp, W tile in registers ----------------
__global__ void logits_kernel(const float* __restrict__ headf,
                              const float* __restrict__ tailf) {
    const int GH = NHN / 4, GT = NTN / 4;          // 50000 % 4 == 0
    int gw   = (blockIdx.x * blockDim.x + threadIdx.x) >> 5;
    int lane = threadIdx.x & 31;
    if (gw >= GH + GT) return;
    const float* src; const float* Wp; float* dst; int r0;
    if (gw < GH) { r0 = gw * 4;        src = headf; Wp = g_Wl; dst = g_hl; }
    else         { r0 = (gw - GH) * 4; src = tailf; Wp = g_Wr; dst = g_hr; }

    float4 w0[NHEAD], w1[NHEAD];
    #pragma unroll
    for (int h = 0; h < NHEAD; h++) {
        const float4* w = reinterpret_cast<const float4*>(Wp + h * INF);
        w0[h] = w[lane]; w1[h] = w[lane + 32];
    }
    #pragma unroll
    for (int rr = 0; rr < 4; rr++) {
        const float4* x = reinterpret_cast<const float4*>(src + (size_t)(r0 + rr) * INF);
        float4 x0 = x[lane], x1 = x[lane + 32];
        float p[NHEAD];
        #pragma unroll
        for (int h = 0; h < NHEAD; h++)
            p[h] = x0.x*w0[h].x + x0.y*w0[h].y + x0.z*w0[h].z + x0.w*w0[h].w
                 + x1.x*w1[h].x + x1.y*w1[h].y + x1.z*w1[h].z + x1.w*w1[h].w;
        #pragma unroll
        for (int off = 16; off; off >>= 1) {
            #pragma unroll
            for (int h = 0; h < NHEAD; h++)
                p[h] += __shfl_xor_sync(0xffffffffu, p[h], off);
        }
        if (lane == 0)
            *reinterpret_cast<float4*>(&dst[(r0 + rr) * NHEAD]) =
                make_float4(p[0], p[1], p[2], p[3]);
    }
}

// ---------------- tail GEMM: h_tail = tail_feature @ W  (50000x256x128) ----------------
// 128x128 block tile, 256 threads, 8x8 per-thread tile, split-column layout for
// conflict-free LDS.128.
__global__ void __launch_bounds__(256, 2)
gemm_tail_kernel(const float* __restrict__ X, const float* __restrict__ W) {
    __shared__ float As[8][128];
    __shared__ float Bs[8][128];
    int tid = threadIdx.x;
    int tx = tid & 15, ty = tid >> 4;
    int rbase = blockIdx.x * 128;

    float acc[8][8];
    #pragma unroll
    for (int i = 0; i < 8; i++)
        #pragma unroll
        for (int j = 0; j < 8; j++) acc[i][j] = 0.f;

    for (int k0 = 0; k0 < INF; k0 += 8) {
        {
            int arow = rbase + (tid >> 1);
            int ar = arow < NTN ? arow : NTN - 1;
            const float4 av = *reinterpret_cast<const float4*>(
                X + (size_t)ar * INF + k0 + (tid & 1) * 4);
            int kp = (tid & 1) * 4;
            int rr = tid >> 1;
            As[kp + 0][rr] = av.x;
            As[kp + 1][rr] = av.y;
            As[kp + 2][rr] = av.z;
            As[kp + 3][rr] = av.w;
        }
        {
            const float4 bv = *reinterpret_cast<const float4*>(
                W + (size_t)(k0 + (tid >> 5)) * FOUT + (tid & 31) * 4);
            *reinterpret_cast<float4*>(&Bs[tid >> 5][(tid & 31) * 4]) = bv;
        }
        __syncthreads();
        #pragma unroll
        for (int kk = 0; kk < 8; kk++) {
            float a[8], b[8];
            float4 t0 = *reinterpret_cast<const float4*>(&As[kk][ty * 4]);
            float4 t1 = *reinterpret_cast<const float4*>(&As[kk][64 + ty * 4]);
            a[0]=t0.x; a[1]=t0.y; a[2]=t0.z; a[3]=t0.w;
            a[4]=t1.x; a[5]=t1.y; a[6]=t1.z; a[7]=t1.w;
            float4 u0 = *reinterpret_cast<const float4*>(&Bs[kk][tx * 4]);
            float4 u1 = *reinterpret_cast<const float4*>(&Bs[kk][64 + tx * 4]);
            b[0]=u0.x; b[1]=u0.y; b[2]=u0.z; b[3]=u0.w;
            b[4]=u1.x; b[5]=u1.y; b[6]=u1.z; b[7]=u1.w;
            #pragma unroll
            for (int i = 0; i < 8; i++)
                #pragma unroll
                for (int j = 0; j < 8; j++)
                    acc[i][j] += a[i] * b[j];
        }
        __syncthreads();
    }
    #pragma unroll
    for (int i = 0; i < 8; i++) {
        int r = rbase + (i < 4 ? ty * 4 + i : 64 + ty * 4 + (i - 4));
        if (r < NTN) {
            *reinterpret_cast<float4*>(&g_htail[(size_t)r * FOUT + tx * 4]) =
                make_float4(acc[i][0], acc[i][1], acc[i][2], acc[i][3]);
            *reinterpret_cast<float4*>(&g_htail[(size_t)r * FOUT + 64 + tx * 4]) =
                make_float4(acc[i][4], acc[i][5], acc[i][6], acc[i][7]);
        }
    }
}

// ---------------- histogram over head indices ----------------
__global__ void hist_kernel(const void* __restrict__ el) {
    int e = blockIdx.x * blockDim.x + threadIdx.x;
    if (e >= NE) return;
    int hi = fetch_idx(el, e, NHN, g_idx64);
    atomicAdd(&g_cnt[hi], 1);
}

// ---------------- single-block exclusive scan -> ptr, cur ----------------
__global__ void __launch_bounds__(1024, 1) scan_kernel() {
    __shared__ int s[1024];
    int t = threadIdx.x;
    const int C = (NHN + 1023) / 1024;   // 49
    int start = t * C;
    int end = start + C; if (end > NHN) end = NHN;
    if (start > NHN) start = NHN;
    int sum = 0;
    for (int i = start; i < end; i++) sum += g_cnt[i];
    s[t] = sum;
    __syncthreads();
    for (int off = 1; off < 1024; off <<= 1) {
        int v = (t >= off) ? s[t - off] : 0;
        __syncthreads();
        s[t] += v;
        __syncthreads();
    }
    int run = s[t] - sum;   // exclusive base for this chunk
    for (int i = start; i < end; i++) {
        int c = g_cnt[i];
        g_ptr[i] = run;
        g_cur[i] = run;
        run += c;
    }
    if (t == 1023) g_ptr[NHN] = run;
}

// ---------------- edge pass A: att -> exp, denom red, sorted scatter ----------------
// No max-subtraction: logits are bounded, exp cannot overflow, and
// alpha = exp(att)/sum(exp(att)) is identical to the max-shifted form.
__global__ void edgeA_kernel(const void* __restrict__ el,
                             const void* __restrict__ te) {
    int e = blockIdx.x * blockDim.x + threadIdx.x;
    if (e >= NE) return;
    int is64 = g_idx64;
    int hi = fetch_idx(el, e, NHN, is64);
    int ti = fetch_idx(el, NE + e, NTN, is64);
    int tt = fetch_idx(te, e, NET, is64);
    float4 l = *reinterpret_cast<const float4*>(&g_hl[hi * NHEAD]);
    float4 r = *reinterpret_cast<const float4*>(&g_hr[ti * NHEAD]);
    float4 h = *reinterpret_cast<const float4*>(&g_he[tt * NHEAD]);
    float4 a;
    a.x = l.x + r.x + h.x; a.x = a.x >= 0.f ? a.x : NSLOPE * a.x;
    a.y = l.y + r.y + h.y; a.y = a.y >= 0.f ? a.y : NSLOPE * a.y;
    a.z = l.z + r.z + h.z; a.z = a.z >= 0.f ? a.z : NSLOPE * a.z;
    a.w = l.w + r.w + h.w; a.w = a.w >= 0.f ? a.w : NSLOPE * a.w;
    float4 ex;
    ex.x = expf(a.x); ex.y = expf(a.y); ex.z = expf(a.z); ex.w = expf(a.w);

    float* dp = &g_den[hi * NHEAD];
    asm volatile("red.global.add.v4.f32 [%0], {%1,%2,%3,%4};"
                 :: "l"(dp), "f"(ex.x), "f"(ex.y), "f"(ex.z), "f"(ex.w)
                 : "memory");

    int pos = atomicAdd(&g_cur[hi], 1);
    SEdge s;
    s.ex[0] = ex.x; s.ex[1] = ex.y; s.ex[2] = ex.z; s.ex[3] = ex.w;
    s.ti = ti; s.e = e; s.pad[0] = 0; s.pad[1] = 0;
    g_srt[pos] = s;
}

// ---------------- edge pass C: warp per head node, atomic-free aggregation ----------------
__global__ void edgeC_kernel(float* __restrict__ out,
                             float* __restrict__ alpha_out,
                             int write_alpha) {
    int node = (blockIdx.x * blockDim.x + threadIdx.x) >> 5;
    int lane = threadIdx.x & 31;
    if (node >= NHN) return;
    int p0 = g_ptr[node], p1 = g_ptr[node + 1];

    float4 den = *reinterpret_cast<const float4*>(&g_den[node * NHEAD]);
    float4 rd;
    rd.x = den.x > 0.f ? 1.f / den.x : 0.f;
    rd.y = den.y > 0.f ? 1.f / den.y : 0.f;
    rd.z = den.z > 0.f ? 1.f / den.z : 0.f;
    rd.w = den.w > 0.f ? 1.f / den.w : 0.f;

    int h = lane >> 3;
    float4 acc = make_float4(0.f, 0.f, 0.f, 0.f);

    for (int j = p0; j < p1; j++) {
        SEdge s = g_srt[j];                       // uniform 32B load (broadcast)
        float4 al = make_float4(s.ex[0] * rd.x, s.ex[1] * rd.y,
                                s.ex[2] * rd.z, s.ex[3] * rd.w);
        if (write_alpha && lane == 0)
            *reinterpret_cast<float4*>(&alpha_out[(size_t)s.e * NHEAD]) = al;
        float a = (h == 0) ? al.x : (h == 1) ? al.y : (h == 2) ? al.z : al.w;
        float4 v = *reinterpret_cast<const float4*>(
            &g_htail[(size_t)s.ti * FOUT + lane * 4]);
        acc.x += a * v.x; acc.y += a * v.y; acc.z += a * v.z; acc.w += a * v.w;
    }

    // fused ELU + store
    acc.x = acc.x > 0.f ? acc.x : expm1f(acc.x);
    acc.y = acc.y > 0.f ? acc.y : expm1f(acc.y);
    acc.z = acc.z > 0.f ? acc.z : expm1f(acc.z);
    acc.w = acc.w > 0.f ? acc.w : expm1f(acc.w);
    *reinterpret_cast<float4*>(&out[(size_t)node * FOUT + lane * 4]) = acc;
}

extern "C" void kernel_launch(void* const* d_in, const int* in_sizes, int n_in,
                              void* d_out, int out_size) {
    const float* headf = (const float*)d_in[0];
    const float* tailf = (const float*)d_in[1];
    const float* W     = (const float*)d_in[2];
    const float* We    = (const float*)d_in[3];
    const float* emb   = (const float*)d_in[4];
    const float* a_l   = (const float*)d_in[5];
    const float* a_r   = (const float*)d_in[6];
    const float* a_e   = (const float*)d_in[7];
    const void*  el    = d_in[8];
    const void*  te    = d_in[9];

    float* out   = (float*)d_out;
    float* alpha = out + (size_t)NHN * FOUT;
    int write_alpha = (out_size >= NHN * FOUT + NE * NHEAD) ? 1 : 0;

    detect_kernel<<<1, 32>>>((const unsigned*)el);
    init_kernel<<<256, 256>>>();
    prep_kernel<<<1, 256>>>(W, We, emb, a_l, a_r, a_e);
    logits_kernel<<<(25000 * 32 + 255) / 256, 256>>>(headf, tailf);
    gemm_tail_kernel<<<(NTN + 127) / 128, 256>>>(tailf, W);
    hist_kernel<<<(NE + 255) / 256, 256>>>(el);
    scan_kernel<<<1, 1024>>>();
    edgeA_kernel<<<(NE + 255) / 256, 256>>>(el, te);
    edgeC_kernel<<<(NHN * 32 + 255) / 256, 256>>>(out, alpha, write_alpha);
}

// round 11
// speedup vs baseline: 1.2229x; 1.0306x over previous
#include <cuda_runtime.h>
#include <math.h>

#define NHN 50000          // head nodes
#define NTN 50000          // tail nodes
#define NE  1600000        // edges
#define INF 256            // in features
#define OUTF 32
#define NHEAD 4
#define EDGEF 64
#define NET 5
#define FOUT 128           // NHEAD*OUTF
#define NSLOPE 0.2f

#define GEMM_BLOCKS ((NTN + 127) / 128)            // 391
#define EDGEA_BLOCKS ((NE + 255) / 256)            // 6250

// packed f32x2 FMA: acc = a2 * b2 + acc  (per-half)
#define FMA2(acc, a2, b2) \
    asm("fma.rn.f32x2 %0, %1, %2, %0;" : "+l"(acc) : "l"(a2), "l"(b2))

// ---------------- sorted edge record (one 32B sector) ----------------
struct __align__(32) SEdge {
    float ex[4];   // exp(att) per head
    int   ti;      // tail index
    int   e;       // original edge id (for alpha output)
    int   pad[2];
};

// ---------------- static scratch ----------------
__device__ __align__(16) float g_htail[(size_t)NTN * FOUT];   // 25.6MB
__device__ __align__(16) float g_hl[NHN * NHEAD];
__device__ __align__(16) float g_hr[NTN * NHEAD];
__device__ __align__(16) float g_he[NET * NHEAD];
__device__ __align__(16) float g_Wl[NHEAD * INF];
__device__ __align__(16) float g_Wr[NHEAD * INF];
__device__ __align__(16) float g_den[NHN * NHEAD];
__device__ int   g_cnt[NHN];
__device__ int   g_ptr[NHN + 1];
__device__ int   g_cur[NHN];
__device__ SEdge g_srt[NE];                                   // 51.2MB
__device__ int   g_hi[NE];                                    // int32 head idx
__device__ int   g_ti[NE];                                    // int32 tail idx
__device__ unsigned char g_tt[NE];                            // edge type
__device__ int   g_idx64;   // 1 if index arrays are int64, 0 if int32

// ---- robust index fetch: works for int32 or int64 input, clamped in-range ----
__device__ __forceinline__ int fetch_idx(const void* buf, int i, int n, int is64) {
    long long v = is64 ? ((const long long*)buf)[i] : (long long)((const int*)buf)[i];
    int r = (int)v;
    if (r < 0) r = 0;
    if (r >= n) r = n - 1;
    return r;
}

// ---------------- dtype detection for index arrays ----------------
__global__ void detect_kernel(const unsigned* __restrict__ el_raw) {
    if (threadIdx.x == 0) {
        int all0 = 1;
        #pragma unroll 8
        for (int i = 0; i < 64; i++)
            if (el_raw[2 * i + 1] != 0u) all0 = 0;
        g_idx64 = all0;
    }
}

// ---------------- tiny prep: folded projection vectors ----------------
__global__ void prep_kernel(const float* __restrict__ W, const float* __restrict__ We,
                            const float* __restrict__ emb,
                            const float* __restrict__ a_l, const float* __restrict__ a_r,
                            const float* __restrict__ a_e) {
    int tid = threadIdx.x;
    for (int idx = tid; idx < NHEAD * INF; idx += blockDim.x) {
        int h = idx >> 8;
        int k = idx & 255;
        float sl = 0.f, sr = 0.f;
        #pragma unroll
        for (int d = 0; d < OUTF; d++) {
            float w = W[k * FOUT + h * OUTF + d];
            sl += w * a_l[h * OUTF + d];
            sr += w * a_r[h * OUTF + d];
        }
        g_Wl[idx] = sl;
        g_Wr[idx] = sr;
    }
    for (int idx = tid; idx < NET * NHEAD; idx += blockDim.x) {
        int t = idx / NHEAD, h = idx % NHEAD;
        float s = 0.f;
        for (int f = 0; f < EDGEF; f++) {
            float ef = 0.f;
            #pragma unroll 8
            for (int k = 0; k < EDGEF; k++)
                ef += emb[t * EDGEF + k] * We[k * (NHEAD * EDGEF) + h * EDGEF + f];
            s += a_e[h * EDGEF + f] * ef;
        }
        g_he[t * NHEAD + h] = s;
    }
}

// ---------------- init: zero den + counts ----------------
__global__ void init_kernel() {
    int i = blockIdx.x * blockDim.x + threadIdx.x;
    int stride = gridDim.x * blockDim.x;
    for (int j = i; j < NHN * NHEAD; j += stride) g_den[j] = 0.f;
    for (int j = i; j < NHN; j += stride) g_cnt[j] = 0;
}

// ---------------- per-node logits: 4 rows per warp, W tile in registers ----------------
__global__ void logits_kernel(const float* __restrict__ headf,
                              const float* __restrict__ tailf) {
    const int GH = NHN / 4, GT = NTN / 4;
    int gw   = (blockIdx.x * blockDim.x + threadIdx.x) >> 5;
    int lane = threadIdx.x & 31;
    if (gw >= GH + GT) return;
    const float* src; const float* Wp; float* dst; int r0;
    if (gw < GH) { r0 = gw * 4;        src = headf; Wp = g_Wl; dst = g_hl; }
    else         { r0 = (gw - GH) * 4; src = tailf; Wp = g_Wr; dst = g_hr; }

    float4 w0[NHEAD], w1[NHEAD];
    #pragma unroll
    for (int h = 0; h < NHEAD; h++) {
        const float4* w = reinterpret_cast<const float4*>(Wp + h * INF);
        w0[h] = w[lane]; w1[h] = w[lane + 32];
    }
    #pragma unroll
    for (int rr = 0; rr < 4; rr++) {
        const float4* x = reinterpret_cast<const float4*>(src + (size_t)(r0 + rr) * INF);
        float4 x0 = x[lane], x1 = x[lane + 32];
        float p[NHEAD];
        #pragma unroll
        for (int h = 0; h < NHEAD; h++)
            p[h] = x0.x*w0[h].x + x0.y*w0[h].y + x0.z*w0[h].z + x0.w*w0[h].w
                 + x1.x*w1[h].x + x1.y*w1[h].y + x1.z*w1[h].z + x1.w*w1[h].w;
        #pragma unroll
        for (int off = 16; off; off >>= 1) {
            #pragma unroll
            for (int h = 0; h < NHEAD; h++)
                p[h] += __shfl_xor_sync(0xffffffffu, p[h], off);
        }
        if (lane == 0)
            *reinterpret_cast<float4*>(&dst[(r0 + rr) * NHEAD]) =
                make_float4(p[0], p[1], p[2], p[3]);
    }
}

// ---------------- hist + index conversion to int32/uint8 ----------------
__global__ void hist_kernel(const void* __restrict__ el,
                            const void* __restrict__ te) {
    int e = blockIdx.x * blockDim.x + threadIdx.x;
    if (e >= NE) return;
    int is64 = g_idx64;
    int hi = fetch_idx(el, e, NHN, is64);
    int ti = fetch_idx(el, NE + e, NTN, is64);
    int tt = fetch_idx(te, e, NET, is64);
    g_hi[e] = hi;
    g_ti[e] = ti;
    g_tt[e] = (unsigned char)tt;
    atomicAdd(&g_cnt[hi], 1);
}

// ---------------- single-block exclusive scan -> ptr, cur ----------------
__global__ void __launch_bounds__(1024, 1) scan_kernel() {
    __shared__ int s[1024];
    int t = threadIdx.x;
    const int C = (NHN + 1023) / 1024;
    int start = t * C;
    int end = start + C; if (end > NHN) end = NHN;
    if (start > NHN) start = NHN;
    int sum = 0;
    for (int i = start; i < end; i++) sum += g_cnt[i];
    s[t] = sum;
    __syncthreads();
    for (int off = 1; off < 1024; off <<= 1) {
        int v = (t >= off) ? s[t - off] : 0;
        __syncthreads();
        s[t] += v;
        __syncthreads();
    }
    int run = s[t] - sum;
    for (int i = start; i < end; i++) {
        int c = g_cnt[i];
        g_ptr[i] = run;
        g_cur[i] = run;
        run += c;
    }
    if (t == 1023) g_ptr[NHN] = run;
}

// ================= FAT kernel: GEMM (blocks [0,391)) ∥ edgeA (rest) =================
__device__ __forceinline__ void gemm_body(const float* __restrict__ X,
                                          const float* __restrict__ W,
                                          int bid, int tid,
                                          float As[8][128], float Bs[8][128]) {
    int tx = tid & 15, ty = tid >> 4;
    int rbase = bid * 128;

    unsigned long long accp[8][4];
    #pragma unroll
    for (int i = 0; i < 8; i++)
        #pragma unroll
        for (int j = 0; j < 4; j++) accp[i][j] = 0ull;

    for (int k0 = 0; k0 < INF; k0 += 8) {
        {
            int arow = rbase + (tid >> 1);
            int ar = arow < NTN ? arow : NTN - 1;
            const float4 av = *reinterpret_cast<const float4*>(
                X + (size_t)ar * INF + k0 + (tid & 1) * 4);
            int kp = (tid & 1) * 4;
            int rr = tid >> 1;
            As[kp + 0][rr] = av.x;
            As[kp + 1][rr] = av.y;
            As[kp + 2][rr] = av.z;
            As[kp + 3][rr] = av.w;
        }
        {
            const float4 bv = *reinterpret_cast<const float4*>(
                W + (size_t)(k0 + (tid >> 5)) * FOUT + (tid & 31) * 4);
            *reinterpret_cast<float4*>(&Bs[tid >> 5][(tid & 31) * 4]) = bv;
        }
        __syncthreads();
        #pragma unroll
        for (int kk = 0; kk < 8; kk++) {
            float a[8];
            float4 t0 = *reinterpret_cast<const float4*>(&As[kk][ty * 4]);
            float4 t1 = *reinterpret_cast<const float4*>(&As[kk][64 + ty * 4]);
            a[0]=t0.x; a[1]=t0.y; a[2]=t0.z; a[3]=t0.w;
            a[4]=t1.x; a[5]=t1.y; a[6]=t1.z; a[7]=t1.w;
            // b pairs as packed 64-bit reads from shared (16B aligned)
            ulonglong2 b01 = *reinterpret_cast<const ulonglong2*>(&Bs[kk][tx * 4]);
            ulonglong2 b23 = *reinterpret_cast<const ulonglong2*>(&Bs[kk][64 + tx * 4]);
            unsigned long long bp0 = b01.x, bp1 = b01.y, bp2 = b23.x, bp3 = b23.y;
            #pragma unroll
            for (int i = 0; i < 8; i++) {
                unsigned long long a2;
                unsigned au = __float_as_uint(a[i]);
                asm("mov.b64 %0, {%1, %1};" : "=l"(a2) : "r"(au));
                FMA2(accp[i][0], a2, bp0);
                FMA2(accp[i][1], a2, bp1);
                FMA2(accp[i][2], a2, bp2);
                FMA2(accp[i][3], a2, bp3);
            }
        }
        __syncthreads();
    }
    #pragma unroll
    for (int i = 0; i < 8; i++) {
        int r = rbase + (i < 4 ? ty * 4 + i : 64 + ty * 4 + (i - 4));
        if (r < NTN) {
            unsigned lo0, hi0, lo1, hi1;
            asm("mov.b64 {%0, %1}, %2;" : "=r"(lo0), "=r"(hi0) : "l"(accp[i][0]));
            asm("mov.b64 {%0, %1}, %2;" : "=r"(lo1), "=r"(hi1) : "l"(accp[i][1]));
            *reinterpret_cast<float4*>(&g_htail[(size_t)r * FOUT + tx * 4]) =
                make_float4(__uint_as_float(lo0), __uint_as_float(hi0),
                            __uint_as_float(lo1), __uint_as_float(hi1));
            asm("mov.b64 {%0, %1}, %2;" : "=r"(lo0), "=r"(hi0) : "l"(accp[i][2]));
            asm("mov.b64 {%0, %1}, %2;" : "=r"(lo1), "=r"(hi1) : "l"(accp[i][3]));
            *reinterpret_cast<float4*>(&g_htail[(size_t)r * FOUT + 64 + tx * 4]) =
                make_float4(__uint_as_float(lo0), __uint_as_float(hi0),
                            __uint_as_float(lo1), __uint_as_float(hi1));
        }
    }
}

__device__ __forceinline__ void edgeA_body(int bid, int tid) {
    int e = bid * 256 + tid;
    if (e >= NE) return;
    int hi = g_hi[e];
    int ti = g_ti[e];
    int tt = (int)g_tt[e];
    float4 l = *reinterpret_cast<const float4*>(&g_hl[hi * NHEAD]);
    float4 r = *reinterpret_cast<const float4*>(&g_hr[ti * NHEAD]);
    float4 h = *reinterpret_cast<const float4*>(&g_he[tt * NHEAD]);
    float4 a;
    a.x = l.x + r.x + h.x; a.x = a.x >= 0.f ? a.x : NSLOPE * a.x;
    a.y = l.y + r.y + h.y; a.y = a.y >= 0.f ? a.y : NSLOPE * a.y;
    a.z = l.z + r.z + h.z; a.z = a.z >= 0.f ? a.z : NSLOPE * a.z;
    a.w = l.w + r.w + h.w; a.w = a.w >= 0.f ? a.w : NSLOPE * a.w;
    float4 ex;
    ex.x = expf(a.x); ex.y = expf(a.y); ex.z = expf(a.z); ex.w = expf(a.w);

    float* dp = &g_den[hi * NHEAD];
    asm volatile("red.global.add.v4.f32 [%0], {%1,%2,%3,%4};"
                 :: "l"(dp), "f"(ex.x), "f"(ex.y), "f"(ex.z), "f"(ex.w)
                 : "memory");

    int pos = atomicAdd(&g_cur[hi], 1);
    SEdge s;
    s.ex[0] = ex.x; s.ex[1] = ex.y; s.ex[2] = ex.z; s.ex[3] = ex.w;
    s.ti = ti; s.e = e; s.pad[0] = 0; s.pad[1] = 0;
    g_srt[pos] = s;
}

__global__ void __launch_bounds__(256, 2)
fat_kernel(const float* __restrict__ X, const float* __restrict__ W) {
    __shared__ float As[8][128];
    __shared__ float Bs[8][128];
    int bid = blockIdx.x;
    int tid = threadIdx.x;
    if (bid < GEMM_BLOCKS) {
        gemm_body(X, W, bid, tid, As, Bs);
    } else {
        edgeA_body(bid - GEMM_BLOCKS, tid);
    }
}

// ---------------- edge pass C: warp per head node, atomic-free aggregation ----------------
__global__ void edgeC_kernel(float* __restrict__ out,
                             float* __restrict__ alpha_out,
                             int write_alpha) {
    int node = (blockIdx.x * blockDim.x + threadIdx.x) >> 5;
    int lane = threadIdx.x & 31;
    if (node >= NHN) return;
    int p0 = g_ptr[node], p1 = g_ptr[node + 1];

    float4 den = *reinterpret_cast<const float4*>(&g_den[node * NHEAD]);
    float4 rd;
    rd.x = den.x > 0.f ? 1.f / den.x : 0.f;
    rd.y = den.y > 0.f ? 1.f / den.y : 0.f;
    rd.z = den.z > 0.f ? 1.f / den.z : 0.f;
    rd.w = den.w > 0.f ? 1.f / den.w : 0.f;

    int h = lane >> 3;
    float4 acc = make_float4(0.f, 0.f, 0.f, 0.f);

    for (int j = p0; j < p1; j++) {
        SEdge s = g_srt[j];                       // uniform 32B load (broadcast)
        float4 al = make_float4(s.ex[0] * rd.x, s.ex[1] * rd.y,
                                s.ex[2] * rd.z, s.ex[3] * rd.w);
        if (write_alpha && lane == 0)
            *reinterpret_cast<float4*>(&alpha_out[(size_t)s.e * NHEAD]) = al;
        float a = (h == 0) ? al.x : (h == 1) ? al.y : (h == 2) ? al.z : al.w;
        float4 v = *reinterpret_cast<const float4*>(
            &g_htail[(size_t)s.ti * FOUT + lane * 4]);
        acc.x += a * v.x; acc.y += a * v.y; acc.z += a * v.z; acc.w += a * v.w;
    }

    // fused ELU + store
    acc.x = acc.x > 0.f ? acc.x : expm1f(acc.x);
    acc.y = acc.y > 0.f ? acc.y : expm1f(acc.y);
    acc.z = acc.z > 0.f ? acc.z : expm1f(acc.z);
    acc.w = acc.w > 0.f ? acc.w : expm1f(acc.w);
    *reinterpret_cast<float4*>(&out[(size_t)node * FOUT + lane * 4]) = acc;
}

extern "C" void kernel_launch(void* const* d_in, const int* in_sizes, int n_in,
                              void* d_out, int out_size) {
    const float* headf = (const float*)d_in[0];
    const float* tailf = (const float*)d_in[1];
    const float* W     = (const float*)d_in[2];
    const float* We    = (const float*)d_in[3];
    const float* emb   = (const float*)d_in[4];
    const float* a_l   = (const float*)d_in[5];
    const float* a_r   = (const float*)d_in[6];
    const float* a_e   = (const float*)d_in[7];
    const void*  el    = d_in[8];
    const void*  te    = d_in[9];

    float* out   = (float*)d_out;
    float* alpha = out + (size_t)NHN * FOUT;
    int write_alpha = (out_size >= NHN * FOUT + NE * NHEAD) ? 1 : 0;

    detect_kernel<<<1, 32>>>((const unsigned*)el);
    init_kernel<<<256, 256>>>();
    prep_kernel<<<1, 256>>>(W, We, emb, a_l, a_r, a_e);
    logits_kernel<<<(25000 * 32 + 255) / 256, 256>>>(headf, tailf);
    hist_kernel<<<(NE + 255) / 256, 256>>>(el, te);
    scan_kernel<<<1, 1024>>>();
    fat_kernel<<<GEMM_BLOCKS + EDGEA_BLOCKS, 256>>>(tailf, W);
    edgeC_kernel<<<(NHN * 32 + 255) / 256, 256>>>(out, alpha, write_alpha);
}